// round 5
// baseline (speedup 1.0000x reference)
#include <cuda_runtime.h>
#include <math.h>

// ---------------------------------------------------------------------------
// ElectricOverflow. Grid 512x512x8 (8MB, L2-resident), padded both sides.
//
// Cost model (validated R4): scatter is bound by RED *instruction issues* +
// divergence overhead, not active-lane count. So:
//  * mf z-emission is branch-free: per (x,y) cell exactly two red.v2 at the
//    8B-aligned window zbase = iz0 & ~1, values parity-selected (SELP).
//    Zero-addend / out-of-range lanes hit border bins (dead: reference
//    overwrites borders with 1.0) or padding (never read).
//  * k_zero is eliminated: k_reduce resets the grid to zero after reading
//    (device globals start zeroed; every replay leaves them zeroed).
// ---------------------------------------------------------------------------

#define NM_ 250000
#define NT_ 8000
#define NF_ 60000
#define N_  (NM_ + NT_ + NF_)    // 318000
#define NX_ 512
#define NY_ 512
#define NZ_ 8
#define NBINS_ (NX_ * NY_ * NZ_) // 2097152
#define PADF_ 4424               // covers ix/iy in [-1,512], z window [-2,9]

#define SQRT2H 0.7071067811865476f
#define C1 0.41421356237309515f  // sqrt2 - 1
#define C2 0.5857864376269049f   // 2 - sqrt2

__device__ float g_pad[PADF_ + NBINS_ + PADF_];
#define GRID_B (g_pad + PADF_)

__device__ __forceinline__ void red1(float* p, float v) {
    asm volatile("red.global.add.f32 [%0], %1;" :: "l"(p), "f"(v) : "memory");
}
__device__ __forceinline__ void red2(float* p, float a, float b) {
    asm volatile("red.global.add.v2.f32 [%0], {%1, %2};"
                 :: "l"(p), "f"(a), "f"(b) : "memory");
}

// ---------------------------------------------------------------------------
// Fused scatter. Threads [0, NM+NF): movable+fixed (clamped size = sqrt2^3,
// centered, weight = volume ratio). Threads [NM+NF, N): fillers (raw size,
// weight 1, <= 2 bins/axis). Thread 0 seeds the outputs (reduce runs after).
// ---------------------------------------------------------------------------
__global__ void k_scatter(const float* __restrict__ pos,
                          const float* __restrict__ nsx,
                          const float* __restrict__ nsy,
                          const float* __restrict__ nsz,
                          float* __restrict__ out) {
    int t = blockIdx.x * blockDim.x + threadIdx.x;
    if (t >= N_) return;
    if (t == 0) { out[0] = 0.0f; out[1] = 1.0f; }   // border density = 1.0

    bool isFill = (t >= NM_ + NF_);
    int j = isFill ? (t - NF_) : ((t < NM_) ? t : (t + NT_));

    float sx = nsx[j], sy = nsy[j], sz = nsz[j];
    float px = pos[j], py = pos[N_ + j], pz = pos[2 * N_ + j];

    if (!isFill) {
        // --- movable/fixed: cs = sqrt2 on every axis ---
        const float w = sx * sy * sz * 0.35355339059327373f;  // /(2*sqrt2)
        float x0 = px + 0.5f * sx - SQRT2H;
        float y0 = py + 0.5f * sy - SQRT2H;
        float z0 = pz + 0.5f * sz - SQRT2H;

        float fxf = floorf(x0), fyf = floorf(y0), fzf = floorf(z0);
        int ix0 = (int)fxf, iy0 = (int)fyf, iz0 = (int)fzf;
        float fx = x0 - fxf, fy = y0 - fyf, fz = z0 - fzf;

        float ox[3] = { 1.0f - fx, fminf(fx + C1, 1.0f), fmaxf(fx - C2, 0.0f) };
        float oy[3] = { 1.0f - fy, fminf(fy + C1, 1.0f), fmaxf(fy - C2, 0.0f) };

        float v0 = 1.0f - fz;
        float v1 = fminf(fz + C1, 1.0f);
        float v2 = fmaxf(fz - C2, 0.0f);

        // 4-wide z window at 8B-aligned base (parity-uniform, branch-free)
        bool even = ((iz0 & 1) == 0);
        int zbase = iz0 & ~1;
        float za0 = even ? v0 : 0.0f;
        float za1 = even ? v1 : v0;
        float za2 = even ? v2 : v1;
        float za3 = even ? 0.0f : v2;

        int rowbase = ((ix0 * NY_ + iy0) << 3) + zbase;
#pragma unroll
        for (int a = 0; a < 3; ++a) {
            if (ox[a] == 0.0f) continue;          // only a==2 can be 0
            float wx = w * ox[a];
#pragma unroll
            for (int b = 0; b < 3; ++b) {
                if (oy[b] == 0.0f) continue;
                float wxy = wx * oy[b];
                float* p = GRID_B + rowbase + ((a * NY_ + b) << 3);
                red2(p,     wxy * za0, wxy * za1);
                red2(p + 2, wxy * za2, wxy * za3);
            }
        }
    } else {
        // --- filler: raw sizes < 1 -> <= 2 bins/axis, weight 1 (8k nodes) ---
        float fxf = floorf(px), fyf = floorf(py), fzf = floorf(pz);
        int ix0 = (int)fxf, iy0 = (int)fyf, iz0 = (int)fzf;  // iz0 in [0,6]
        float fx = px - fxf, fy = py - fyf, fz = pz - fzf;

        float ox[2] = { fminf(1.0f - fx, sx), fmaxf(fx + sx - 1.0f, 0.0f) };
        float oy[2] = { fminf(1.0f - fy, sy), fmaxf(fy + sy - 1.0f, 0.0f) };
        float v0 = fminf(1.0f - fz, sz);
        float v1 = fmaxf(fz + sz - 1.0f, 0.0f);
        bool e0 = (iz0 >= 1);                       // bin iz0 interior
        bool e1 = (iz0 <= 5) & (v1 > 0.0f);         // bin iz0+1 interior
        if (!(e0 | e1)) return;
        bool even0 = ((iz0 & 1) == 0);

#pragma unroll
        for (int a = 0; a < 2; ++a) {
            if (ox[a] == 0.0f) continue;
#pragma unroll
            for (int b = 0; b < 2; ++b) {
                if (oy[b] == 0.0f) continue;
                float wxy = ox[a] * oy[b];
                float* p = GRID_B + (((ix0 + a) * NY_ + (iy0 + b)) << 3) + iz0;
                if (e0 && e1 && even0) red2(p, wxy * v0, wxy * v1);
                else {
                    if (e0) red1(p, wxy * v0);
                    if (e1) red1(p + 1, wxy * v1);
                }
            }
        }
    }
}

// ---------------------------------------------------------------------------
// Reduction WITH RESET: one thread per (x,y) z-row. Loads 2x float4
// (interior z=1..6 contribute), then stores zeros back so the grid is
// pristine for the next graph replay. Border rows are reset too (scatter
// alias lanes write real values there).
// ---------------------------------------------------------------------------
__global__ void k_reduce(float* __restrict__ out) {
    int t = blockIdx.x * blockDim.x + threadIdx.x;  // 512*512 threads
    float4* g4 = reinterpret_cast<float4*>(GRID_B) + t * 2;
    float4 a = g4[0];
    float4 b = g4[1];
    const float4 z = make_float4(0.f, 0.f, 0.f, 0.f);
    g4[0] = z;
    g4[1] = z;

    float s = 0.0f, m = 0.0f;
    int ix = t >> 9;
    int iy = t & 511;
    if (ix >= 1 && ix <= NX_ - 2 && iy >= 1 && iy <= NY_ - 2) {
        s = fmaxf(a.y - 1.0f, 0.0f) + fmaxf(a.z - 1.0f, 0.0f) +
            fmaxf(a.w - 1.0f, 0.0f) + fmaxf(b.x - 1.0f, 0.0f) +
            fmaxf(b.y - 1.0f, 0.0f) + fmaxf(b.z - 1.0f, 0.0f);
        m = fmaxf(fmaxf(fmaxf(a.y, a.z), fmaxf(a.w, b.x)), fmaxf(b.y, b.z));
    }
#pragma unroll
    for (int o = 16; o > 0; o >>= 1) {
        s += __shfl_down_sync(0xffffffffu, s, o);
        m = fmaxf(m, __shfl_down_sync(0xffffffffu, m, o));
    }
    __shared__ float ss[8], sm[8];
    int lane = threadIdx.x & 31;
    int wid = threadIdx.x >> 5;
    if (lane == 0) { ss[wid] = s; sm[wid] = m; }
    __syncthreads();
    if (wid == 0) {
        int nw = blockDim.x >> 5;
        s = (lane < nw) ? ss[lane] : 0.0f;
        m = (lane < nw) ? sm[lane] : 0.0f;
#pragma unroll
        for (int o = 4; o > 0; o >>= 1) {
            s += __shfl_down_sync(0xffffffffu, s, o);
            m = fmaxf(m, __shfl_down_sync(0xffffffffu, m, o));
        }
        if (lane == 0) {
            atomicAdd(&out[0], s);
            atomicMax(reinterpret_cast<int*>(&out[1]), __float_as_int(m));
        }
    }
}

extern "C" void kernel_launch(void* const* d_in, const int* in_sizes, int n_in,
                              void* d_out, int out_size) {
    const float* pos = (const float*)d_in[0];
    const float* nsx = (const float*)d_in[1];
    const float* nsy = (const float*)d_in[2];
    const float* nsz = (const float*)d_in[3];
    float* out = (float*)d_out;

    k_scatter<<<(N_ + 255) / 256, 256>>>(pos, nsx, nsy, nsz, out);
    k_reduce<<<(NX_ * NY_) / 256, 256>>>(out);
}

// round 6
// speedup vs baseline: 1.1117x; 1.1117x over previous
#include <cuda_runtime.h>
#include <math.h>

// ---------------------------------------------------------------------------
// ElectricOverflow. Grid 512x512x8 (8MB, L2-resident), padded both sides.
// Config = best-known (R4): zero -> scatter (z-border-culled emission) ->
// load-only reduce. A 4th no-op kernel shifts ncu's fixed capture index
// (-s 5, 4 kernels/replay -> idx 5 = scatter) so the scatter finally gets
// profiled. Cost model so far: RED lane/instruction count is NOT the
// binding constraint (R3/R4/R5 all neutral) -> suspect LTS sector-op floor.
// ---------------------------------------------------------------------------

#define NM_ 250000
#define NT_ 8000
#define NF_ 60000
#define N_  (NM_ + NT_ + NF_)    // 318000
#define NX_ 512
#define NY_ 512
#define NZ_ 8
#define NBINS_ (NX_ * NY_ * NZ_) // 2097152
#define PADF_ 4424               // covers ix/iy in [-1,512], z in [1,6]

#define SQRT2H 0.7071067811865476f
#define C1 0.41421356237309515f  // sqrt2 - 1
#define C2 0.5857864376269049f   // 2 - sqrt2

__device__ float g_pad[PADF_ + NBINS_ + PADF_];
#define GRID_B (g_pad + PADF_)

__device__ __forceinline__ void red1(float* p, float v) {
    asm volatile("red.global.add.f32 [%0], %1;" :: "l"(p), "f"(v) : "memory");
}
__device__ __forceinline__ void red2(float* p, float a, float b) {
    asm volatile("red.global.add.v2.f32 [%0], {%1, %2};"
                 :: "l"(p), "f"(a), "f"(b) : "memory");
}

// ---------------------------------------------------------------------------
__global__ void k_zero(float* __restrict__ out) {
    int i = blockIdx.x * blockDim.x + threadIdx.x;  // 131072 threads
    float4* g4 = reinterpret_cast<float4*>(GRID_B);
    const float4 z = make_float4(0.f, 0.f, 0.f, 0.f);
#pragma unroll
    for (int k = 0; k < 4; ++k) g4[i + k * 131072] = z;
    if (i == 0) { out[0] = 0.0f; out[1] = 1.0f; }   // border density = 1.0
}

// Emit up to 3 z-lane REDs, pairing adjacent surviving lanes when 8B-aligned.
__device__ __forceinline__ void emit_z(float* p, float wxy,
                                       float v0, float v1, float v2,
                                       bool e0, bool e1, bool e2, bool even0) {
    if (e0 && e1 && even0) {
        red2(p, wxy * v0, wxy * v1);
        if (e2) red1(p + 2, wxy * v2);
    } else {
        if (e0) red1(p, wxy * v0);
        if (e1 && e2 && !even0) red2(p + 1, wxy * v1, wxy * v2);
        else {
            if (e1) red1(p + 1, wxy * v1);
            if (e2) red1(p + 2, wxy * v2);
        }
    }
}

// ---------------------------------------------------------------------------
// Fused scatter. Threads [0, NM+NF): movable+fixed (clamped size sqrt2^3,
// centered, weight = volume ratio). Threads [NM+NF, N): fillers.
// z-border lanes culled (reference overwrites border bins with 1.0);
// x/y out-of-range lanes alias into padding (never read).
// ---------------------------------------------------------------------------
__global__ void k_scatter(const float* __restrict__ pos,
                          const float* __restrict__ nsx,
                          const float* __restrict__ nsy,
                          const float* __restrict__ nsz) {
    int t = blockIdx.x * blockDim.x + threadIdx.x;
    if (t >= N_) return;

    bool isFill = (t >= NM_ + NF_);
    int j = isFill ? (t - NF_) : ((t < NM_) ? t : (t + NT_));

    float sx = nsx[j], sy = nsy[j], sz = nsz[j];
    float px = pos[j], py = pos[N_ + j], pz = pos[2 * N_ + j];

    if (!isFill) {
        const float w = sx * sy * sz * 0.35355339059327373f;  // /(2*sqrt2)
        float x0 = px + 0.5f * sx - SQRT2H;
        float y0 = py + 0.5f * sy - SQRT2H;
        float z0 = pz + 0.5f * sz - SQRT2H;

        float fxf = floorf(x0), fyf = floorf(y0), fzf = floorf(z0);
        int ix0 = (int)fxf, iy0 = (int)fyf, iz0 = (int)fzf;
        float fx = x0 - fxf, fy = y0 - fyf, fz = z0 - fzf;

        float ox[3] = { 1.0f - fx, fminf(fx + C1, 1.0f), fmaxf(fx - C2, 0.0f) };
        float oy[3] = { 1.0f - fy, fminf(fy + C1, 1.0f), fmaxf(fy - C2, 0.0f) };

        float v0 = 1.0f - fz;
        float v1 = fminf(fz + C1, 1.0f);
        float v2 = fmaxf(fz - C2, 0.0f);
        bool e0 = (iz0 >= 1) & (iz0 <= 6);
        bool e1 = (iz0 >= 0) & (iz0 <= 5);
        bool e2 = (iz0 >= -1) & (iz0 <= 4) & (v2 > 0.0f);
        if (!(e0 | e1 | e2)) return;
        bool even0 = ((iz0 & 1) == 0);

#pragma unroll
        for (int a = 0; a < 3; ++a) {
            if (ox[a] == 0.0f) continue;          // only a==2 can be 0
            float wx = w * ox[a];
#pragma unroll
            for (int b = 0; b < 3; ++b) {
                if (oy[b] == 0.0f) continue;
                float* p = GRID_B + (((ix0 + a) * NY_ + (iy0 + b)) << 3) + iz0;
                emit_z(p, wx * oy[b], v0, v1, v2, e0, e1, e2, even0);
            }
        }
    } else {
        float fxf = floorf(px), fyf = floorf(py), fzf = floorf(pz);
        int ix0 = (int)fxf, iy0 = (int)fyf, iz0 = (int)fzf;  // iz0 in [0,6]
        float fx = px - fxf, fy = py - fyf, fz = pz - fzf;

        float ox[2] = { fminf(1.0f - fx, sx), fmaxf(fx + sx - 1.0f, 0.0f) };
        float oy[2] = { fminf(1.0f - fy, sy), fmaxf(fy + sy - 1.0f, 0.0f) };
        float v0 = fminf(1.0f - fz, sz);
        float v1 = fmaxf(fz + sz - 1.0f, 0.0f);
        bool e0 = (iz0 >= 1);
        bool e1 = (iz0 <= 5) & (v1 > 0.0f);
        if (!(e0 | e1)) return;
        bool even0 = ((iz0 & 1) == 0);

#pragma unroll
        for (int a = 0; a < 2; ++a) {
            if (ox[a] == 0.0f) continue;
#pragma unroll
            for (int b = 0; b < 2; ++b) {
                if (oy[b] == 0.0f) continue;
                float wxy = ox[a] * oy[b];
                float* p = GRID_B + (((ix0 + a) * NY_ + (iy0 + b)) << 3) + iz0;
                if (e0 && e1 && even0) red2(p, wxy * v0, wxy * v1);
                else {
                    if (e0) red1(p, wxy * v0);
                    if (e1) red1(p + 1, wxy * v1);
                }
            }
        }
    }
}

// ---------------------------------------------------------------------------
// Reduction (load-only): one thread per (x,y) z-row, 2x float4, interior
// z=1..6. Border rows skipped (cost 0; max floor 1.0 seeded in k_zero).
// ---------------------------------------------------------------------------
__global__ void k_reduce(float* __restrict__ out) {
    int t = blockIdx.x * blockDim.x + threadIdx.x;  // 512*512 threads
    float s = 0.0f, m = 0.0f;
    int ix = t >> 9;
    int iy = t & 511;
    if (ix >= 1 && ix <= NX_ - 2 && iy >= 1 && iy <= NY_ - 2) {
        const float4* g4 = reinterpret_cast<const float4*>(GRID_B) + t * 2;
        float4 a = g4[0];
        float4 b = g4[1];
        s = fmaxf(a.y - 1.0f, 0.0f) + fmaxf(a.z - 1.0f, 0.0f) +
            fmaxf(a.w - 1.0f, 0.0f) + fmaxf(b.x - 1.0f, 0.0f) +
            fmaxf(b.y - 1.0f, 0.0f) + fmaxf(b.z - 1.0f, 0.0f);
        m = fmaxf(fmaxf(fmaxf(a.y, a.z), fmaxf(a.w, b.x)), fmaxf(b.y, b.z));
    }
#pragma unroll
    for (int o = 16; o > 0; o >>= 1) {
        s += __shfl_down_sync(0xffffffffu, s, o);
        m = fmaxf(m, __shfl_down_sync(0xffffffffu, m, o));
    }
    __shared__ float ss[8], sm[8];
    int lane = threadIdx.x & 31;
    int wid = threadIdx.x >> 5;
    if (lane == 0) { ss[wid] = s; sm[wid] = m; }
    __syncthreads();
    if (wid == 0) {
        int nw = blockDim.x >> 5;
        s = (lane < nw) ? ss[lane] : 0.0f;
        m = (lane < nw) ? sm[lane] : 0.0f;
#pragma unroll
        for (int o = 4; o > 0; o >>= 1) {
            s += __shfl_down_sync(0xffffffffu, s, o);
            m = fmaxf(m, __shfl_down_sync(0xffffffffu, m, o));
        }
        if (lane == 0) {
            atomicAdd(&out[0], s);
            atomicMax(reinterpret_cast<int*>(&out[1]), __float_as_int(m));
        }
    }
}

// 4th kernel: shifts ncu's fixed capture index (-s 5) onto k_scatter.
// Writes a padding slot that is never read; deterministic and harmless.
__global__ void k_noop() {
    if (threadIdx.x == 0) g_pad[0] = 0.0f;
}

extern "C" void kernel_launch(void* const* d_in, const int* in_sizes, int n_in,
                              void* d_out, int out_size) {
    const float* pos = (const float*)d_in[0];
    const float* nsx = (const float*)d_in[1];
    const float* nsy = (const float*)d_in[2];
    const float* nsz = (const float*)d_in[3];
    float* out = (float*)d_out;

    k_zero<<<512, 256>>>(out);
    k_scatter<<<(N_ + 255) / 256, 256>>>(pos, nsx, nsy, nsz);
    k_reduce<<<(NX_ * NY_) / 256, 256>>>(out);
    k_noop<<<1, 32>>>();
}

// round 7
// speedup vs baseline: 1.1390x; 1.0245x over previous
#include <cuda_runtime.h>
#include <math.h>

// ---------------------------------------------------------------------------
// ElectricOverflow. Grid 512x512x8 (8MB, L2-resident), padded both sides.
//
// Launch order [scatter, reduce, zero]: device globals start zeroed and the
// trailing zero-kernel restores that invariant each replay, so the graph is
// replay-deterministic. This ordering also places the scatter at overall
// launch index 3 = ncu's fixed capture slot, so the dominant kernel finally
// gets profiled.
//
// Validated cost model so far: RED lane/instruction count variations are all
// neutral -> suspect LTS atomic sector-op floor. This round measures it.
// ---------------------------------------------------------------------------

#define NM_ 250000
#define NT_ 8000
#define NF_ 60000
#define N_  (NM_ + NT_ + NF_)    // 318000
#define NX_ 512
#define NY_ 512
#define NZ_ 8
#define NBINS_ (NX_ * NY_ * NZ_) // 2097152
#define PADF_ 4424               // covers ix/iy in [-1,512], z in [1,6]

#define SQRT2H 0.7071067811865476f
#define C1 0.41421356237309515f  // sqrt2 - 1
#define C2 0.5857864376269049f   // 2 - sqrt2

__device__ float g_pad[PADF_ + NBINS_ + PADF_];
#define GRID_B (g_pad + PADF_)

__device__ __forceinline__ void red1(float* p, float v) {
    asm volatile("red.global.add.f32 [%0], %1;" :: "l"(p), "f"(v) : "memory");
}
__device__ __forceinline__ void red2(float* p, float a, float b) {
    asm volatile("red.global.add.v2.f32 [%0], {%1, %2};"
                 :: "l"(p), "f"(a), "f"(b) : "memory");
}

// Emit up to 3 z-lane REDs, pairing adjacent surviving lanes when 8B-aligned.
__device__ __forceinline__ void emit_z(float* p, float wxy,
                                       float v0, float v1, float v2,
                                       bool e0, bool e1, bool e2, bool even0) {
    if (e0 && e1 && even0) {
        red2(p, wxy * v0, wxy * v1);
        if (e2) red1(p + 2, wxy * v2);
    } else {
        if (e0) red1(p, wxy * v0);
        if (e1 && e2 && !even0) red2(p + 1, wxy * v1, wxy * v2);
        else {
            if (e1) red1(p + 1, wxy * v1);
            if (e2) red1(p + 2, wxy * v2);
        }
    }
}

// ---------------------------------------------------------------------------
// Fused scatter. Threads [0, NM+NF): movable+fixed (clamped size sqrt2^3,
// centered, weight = volume ratio). Threads [NM+NF, N): fillers.
// z-border lanes culled (reference overwrites border bins with 1.0);
// x/y out-of-range lanes alias into padding (never read).
// Thread 0 seeds the outputs (reduce runs after scatter).
// ---------------------------------------------------------------------------
__global__ void k_scatter(const float* __restrict__ pos,
                          const float* __restrict__ nsx,
                          const float* __restrict__ nsy,
                          const float* __restrict__ nsz,
                          float* __restrict__ out) {
    int t = blockIdx.x * blockDim.x + threadIdx.x;
    if (t >= N_) return;
    if (t == 0) { out[0] = 0.0f; out[1] = 1.0f; }   // border density = 1.0

    bool isFill = (t >= NM_ + NF_);
    int j = isFill ? (t - NF_) : ((t < NM_) ? t : (t + NT_));

    float sx = nsx[j], sy = nsy[j], sz = nsz[j];
    float px = pos[j], py = pos[N_ + j], pz = pos[2 * N_ + j];

    if (!isFill) {
        const float w = sx * sy * sz * 0.35355339059327373f;  // /(2*sqrt2)
        float x0 = px + 0.5f * sx - SQRT2H;
        float y0 = py + 0.5f * sy - SQRT2H;
        float z0 = pz + 0.5f * sz - SQRT2H;

        float fxf = floorf(x0), fyf = floorf(y0), fzf = floorf(z0);
        int ix0 = (int)fxf, iy0 = (int)fyf, iz0 = (int)fzf;
        float fx = x0 - fxf, fy = y0 - fyf, fz = z0 - fzf;

        float ox[3] = { 1.0f - fx, fminf(fx + C1, 1.0f), fmaxf(fx - C2, 0.0f) };
        float oy[3] = { 1.0f - fy, fminf(fy + C1, 1.0f), fmaxf(fy - C2, 0.0f) };

        float v0 = 1.0f - fz;
        float v1 = fminf(fz + C1, 1.0f);
        float v2 = fmaxf(fz - C2, 0.0f);
        bool e0 = (iz0 >= 1) & (iz0 <= 6);
        bool e1 = (iz0 >= 0) & (iz0 <= 5);
        bool e2 = (iz0 >= -1) & (iz0 <= 4) & (v2 > 0.0f);
        if (!(e0 | e1 | e2)) return;
        bool even0 = ((iz0 & 1) == 0);

#pragma unroll
        for (int a = 0; a < 3; ++a) {
            if (ox[a] == 0.0f) continue;          // only a==2 can be 0
            float wx = w * ox[a];
#pragma unroll
            for (int b = 0; b < 3; ++b) {
                if (oy[b] == 0.0f) continue;
                float* p = GRID_B + (((ix0 + a) * NY_ + (iy0 + b)) << 3) + iz0;
                emit_z(p, wx * oy[b], v0, v1, v2, e0, e1, e2, even0);
            }
        }
    } else {
        float fxf = floorf(px), fyf = floorf(py), fzf = floorf(pz);
        int ix0 = (int)fxf, iy0 = (int)fyf, iz0 = (int)fzf;  // iz0 in [0,6]
        float fx = px - fxf, fy = py - fyf, fz = pz - fzf;

        float ox[2] = { fminf(1.0f - fx, sx), fmaxf(fx + sx - 1.0f, 0.0f) };
        float oy[2] = { fminf(1.0f - fy, sy), fmaxf(fy + sy - 1.0f, 0.0f) };
        float v0 = fminf(1.0f - fz, sz);
        float v1 = fmaxf(fz + sz - 1.0f, 0.0f);
        bool e0 = (iz0 >= 1);
        bool e1 = (iz0 <= 5) & (v1 > 0.0f);
        if (!(e0 | e1)) return;
        bool even0 = ((iz0 & 1) == 0);

#pragma unroll
        for (int a = 0; a < 2; ++a) {
            if (ox[a] == 0.0f) continue;
#pragma unroll
            for (int b = 0; b < 2; ++b) {
                if (oy[b] == 0.0f) continue;
                float wxy = ox[a] * oy[b];
                float* p = GRID_B + (((ix0 + a) * NY_ + (iy0 + b)) << 3) + iz0;
                if (e0 && e1 && even0) red2(p, wxy * v0, wxy * v1);
                else {
                    if (e0) red1(p, wxy * v0);
                    if (e1) red1(p + 1, wxy * v1);
                }
            }
        }
    }
}

// ---------------------------------------------------------------------------
// Reduction (load-only): one thread per (x,y) z-row, 2x float4, interior
// z=1..6. Border rows skipped (cost 0; max floor 1.0 seeded in k_scatter).
// ---------------------------------------------------------------------------
__global__ void k_reduce(float* __restrict__ out) {
    int t = blockIdx.x * blockDim.x + threadIdx.x;  // 512*512 threads
    float s = 0.0f, m = 0.0f;
    int ix = t >> 9;
    int iy = t & 511;
    if (ix >= 1 && ix <= NX_ - 2 && iy >= 1 && iy <= NY_ - 2) {
        const float4* g4 = reinterpret_cast<const float4*>(GRID_B) + t * 2;
        float4 a = g4[0];
        float4 b = g4[1];
        s = fmaxf(a.y - 1.0f, 0.0f) + fmaxf(a.z - 1.0f, 0.0f) +
            fmaxf(a.w - 1.0f, 0.0f) + fmaxf(b.x - 1.0f, 0.0f) +
            fmaxf(b.y - 1.0f, 0.0f) + fmaxf(b.z - 1.0f, 0.0f);
        m = fmaxf(fmaxf(fmaxf(a.y, a.z), fmaxf(a.w, b.x)), fmaxf(b.y, b.z));
    }
#pragma unroll
    for (int o = 16; o > 0; o >>= 1) {
        s += __shfl_down_sync(0xffffffffu, s, o);
        m = fmaxf(m, __shfl_down_sync(0xffffffffu, m, o));
    }
    __shared__ float ss[8], sm[8];
    int lane = threadIdx.x & 31;
    int wid = threadIdx.x >> 5;
    if (lane == 0) { ss[wid] = s; sm[wid] = m; }
    __syncthreads();
    if (wid == 0) {
        int nw = blockDim.x >> 5;
        s = (lane < nw) ? ss[lane] : 0.0f;
        m = (lane < nw) ? sm[lane] : 0.0f;
#pragma unroll
        for (int o = 4; o > 0; o >>= 1) {
            s += __shfl_down_sync(0xffffffffu, s, o);
            m = fmaxf(m, __shfl_down_sync(0xffffffffu, m, o));
        }
        if (lane == 0) {
            atomicAdd(&out[0], s);
            atomicMax(reinterpret_cast<int*>(&out[1]), __float_as_int(m));
        }
    }
}

// ---------------------------------------------------------------------------
// Trailing zero: restores the all-zero grid invariant for the next replay
// (and for the post-timing validation run). Runs AFTER reduce.
// ---------------------------------------------------------------------------
__global__ void k_zero() {
    int i = blockIdx.x * blockDim.x + threadIdx.x;  // 131072 threads
    float4* g4 = reinterpret_cast<float4*>(GRID_B);
    const float4 z = make_float4(0.f, 0.f, 0.f, 0.f);
#pragma unroll
    for (int k = 0; k < 4; ++k) g4[i + k * 131072] = z;
}

extern "C" void kernel_launch(void* const* d_in, const int* in_sizes, int n_in,
                              void* d_out, int out_size) {
    const float* pos = (const float*)d_in[0];
    const float* nsx = (const float*)d_in[1];
    const float* nsy = (const float*)d_in[2];
    const float* nsz = (const float*)d_in[3];
    float* out = (float*)d_out;

    k_scatter<<<(N_ + 255) / 256, 256>>>(pos, nsx, nsy, nsz, out);
    k_reduce<<<(NX_ * NY_) / 256, 256>>>(out);
    k_zero<<<512, 256>>>();
}